// round 4
// baseline (speedup 1.0000x reference)
#include <cuda_runtime.h>
#include <math.h>
#include <stdint.h>

// Problem constants
constexpr int Bc  = 2;
constexpr int Sc  = 2048;
constexpr int Dc  = 1024;
constexpr int Hc  = 16;
constexpr int HDc = 64;
constexpr int Mc  = Bc * Sc;          // 4096 rows for projections

// ---------------------------------------------------------------------------
// Device scratch (allocations forbidden; use __device__ globals)
// ---------------------------------------------------------------------------
__device__ float g_q[(size_t)Bc * Sc * Dc];
__device__ float g_k[(size_t)Bc * Sc * Dc];
__device__ float g_v[(size_t)Bc * Sc * Dc];
__device__ float g_ctx[(size_t)Bc * Sc * Dc];

// ---------------------------------------------------------------------------
// Helpers
// ---------------------------------------------------------------------------
__device__ __forceinline__ uint32_t f2tf32(float f) {
    uint32_t u;
    asm("cvt.rna.tf32.f32 %0, %1;" : "=r"(u) : "f"(f));
    return u;
}
__device__ __forceinline__ float f2tf32f(float f) {
    return __uint_as_float(f2tf32(f));
}

// D += A(16x8, tf32) * B(8x8, tf32)   (m16n8k8, row.col)
__device__ __forceinline__ void mma_tf32(float* d, const uint32_t* a, const uint32_t* b) {
    asm volatile(
        "mma.sync.aligned.m16n8k8.row.col.f32.tf32.tf32.f32 "
        "{%0,%1,%2,%3}, {%4,%5,%6,%7}, {%8,%9}, {%0,%1,%2,%3};"
        : "+f"(d[0]), "+f"(d[1]), "+f"(d[2]), "+f"(d[3])
        : "r"(a[0]), "r"(a[1]), "r"(a[2]), "r"(a[3]), "r"(b[0]), "r"(b[1]));
}

// ---------------------------------------------------------------------------
// tf32 GEMM (NT), 3 problems fused via blockIdx.z:
//   Cz[m,n] = sum_k A[m,k] * Wz[n,k] + bz[n]
// BM=128, BN=64, BK=32, 256 threads = 8 warps (4m x 2n), warp tile 32x32.
// ---------------------------------------------------------------------------
__global__ __launch_bounds__(256) void gemm3_tf32_nt_bias(
    const float* __restrict__ A,
    const float* __restrict__ W0, const float* __restrict__ b0, float* __restrict__ C0,
    const float* __restrict__ W1, const float* __restrict__ b1, float* __restrict__ C1,
    const float* __restrict__ W2, const float* __restrict__ b2, float* __restrict__ C2,
    int M, int N, int K)
{
    const int z = blockIdx.z;
    const float* B    = (z == 0) ? W0 : (z == 1) ? W1 : W2;
    const float* bias = (z == 0) ? b0 : (z == 1) ? b1 : b2;
    float*       C    = (z == 0) ? C0 : (z == 1) ? C1 : C2;

    __shared__ float As[128][36];
    __shared__ float Bs[64][36];

    const int tid  = threadIdx.x;
    const int lane = tid & 31;
    const int warp = tid >> 5;
    const int wm   = warp >> 1;          // 0..3
    const int wn   = warp & 1;           // 0..1
    const int g    = lane >> 2;          // 0..7
    const int t    = lane & 3;           // 0..3
    const int bm   = blockIdx.y * 128;
    const int bn   = blockIdx.x * 64;

    float acc[2][4][4];
#pragma unroll
    for (int mt = 0; mt < 2; mt++)
#pragma unroll
        for (int nt = 0; nt < 4; nt++)
#pragma unroll
            for (int i = 0; i < 4; i++) acc[mt][nt][i] = 0.f;

    float4 aReg[4], bReg[2];

#pragma unroll
    for (int i = 0; i < 4; i++) {
        const int f   = tid + i * 256;
        const int row = f >> 3;
        const int c4  = (f & 7) * 4;
        aReg[i] = *(const float4*)(A + (size_t)(bm + row) * K + c4);
    }
#pragma unroll
    for (int i = 0; i < 2; i++) {
        const int f   = tid + i * 256;
        const int row = f >> 3;
        const int c4  = (f & 7) * 4;
        bReg[i] = *(const float4*)(B + (size_t)(bn + row) * K + c4);
    }

    for (int k0 = 0; k0 < K; k0 += 32) {
        __syncthreads();
#pragma unroll
        for (int i = 0; i < 4; i++) {
            const int f   = tid + i * 256;
            const int row = f >> 3;
            const int c4  = (f & 7) * 4;
            As[row][c4 + 0] = f2tf32f(aReg[i].x);
            As[row][c4 + 1] = f2tf32f(aReg[i].y);
            As[row][c4 + 2] = f2tf32f(aReg[i].z);
            As[row][c4 + 3] = f2tf32f(aReg[i].w);
        }
#pragma unroll
        for (int i = 0; i < 2; i++) {
            const int f   = tid + i * 256;
            const int row = f >> 3;
            const int c4  = (f & 7) * 4;
            Bs[row][c4 + 0] = f2tf32f(bReg[i].x);
            Bs[row][c4 + 1] = f2tf32f(bReg[i].y);
            Bs[row][c4 + 2] = f2tf32f(bReg[i].z);
            Bs[row][c4 + 3] = f2tf32f(bReg[i].w);
        }
        __syncthreads();

        if (k0 + 32 < K) {
#pragma unroll
            for (int i = 0; i < 4; i++) {
                const int f   = tid + i * 256;
                const int row = f >> 3;
                const int c4  = (f & 7) * 4;
                aReg[i] = *(const float4*)(A + (size_t)(bm + row) * K + k0 + 32 + c4);
            }
#pragma unroll
            for (int i = 0; i < 2; i++) {
                const int f   = tid + i * 256;
                const int row = f >> 3;
                const int c4  = (f & 7) * 4;
                bReg[i] = *(const float4*)(B + (size_t)(bn + row) * K + k0 + 32 + c4);
            }
        }

#pragma unroll
        for (int ks = 0; ks < 4; ks++) {
            uint32_t af[2][4], bf[4][2];
#pragma unroll
            for (int mt = 0; mt < 2; mt++) {
                const int r = wm * 32 + mt * 16 + g;
                af[mt][0] = __float_as_uint(As[r    ][ks * 8 + t    ]);
                af[mt][1] = __float_as_uint(As[r + 8][ks * 8 + t    ]);
                af[mt][2] = __float_as_uint(As[r    ][ks * 8 + t + 4]);
                af[mt][3] = __float_as_uint(As[r + 8][ks * 8 + t + 4]);
            }
#pragma unroll
            for (int nt = 0; nt < 4; nt++) {
                const int c = wn * 32 + nt * 8 + g;
                bf[nt][0] = __float_as_uint(Bs[c][ks * 8 + t    ]);
                bf[nt][1] = __float_as_uint(Bs[c][ks * 8 + t + 4]);
            }
#pragma unroll
            for (int mt = 0; mt < 2; mt++)
#pragma unroll
                for (int nt = 0; nt < 4; nt++)
                    mma_tf32(acc[mt][nt], af[mt], bf[nt]);
        }
    }

#pragma unroll
    for (int mt = 0; mt < 2; mt++) {
#pragma unroll
        for (int nt = 0; nt < 4; nt++) {
            const int row = bm + wm * 32 + mt * 16 + g;
            const int col = bn + wn * 32 + nt * 8 + 2 * t;
            const float2 bv = *(const float2*)(bias + col);
            float2 o0, o1;
            o0.x = acc[mt][nt][0] + bv.x;
            o0.y = acc[mt][nt][1] + bv.y;
            o1.x = acc[mt][nt][2] + bv.x;
            o1.y = acc[mt][nt][3] + bv.y;
            *(float2*)(C + (size_t)row * N + col)       = o0;
            *(float2*)(C + (size_t)(row + 8) * N + col) = o1;
        }
    }
}

// ---------------------------------------------------------------------------
// Fused two-pass flash attention (recompute; no raw-score round-trip):
//   pass 1: S = Q@K^T (tf32 mma), online row max m / sum Z. Nothing written.
//   pass 2: recompute S bit-identically, P = exp(S-m)*invZ written directly
//           to attn, ctx += P@V. ctx needs no final rescale.
// K stored in smem with paired columns so B-fragments are one LDS.64:
//   col c = ks*8 + t + 4*half  ->  col' = ks*8 + 2*t + half
// ---------------------------------------------------------------------------
constexpr int AT_Q = 64;     // q rows per block (4 warps x 16 rows)
constexpr int K_LD = 72;     // paired-col K stride; frag word-bank = 4g+t (CF)
constexpr int V_LD = 72;     // V row stride; frag bank = 8t+g (CF)

__device__ __forceinline__ int kcol_pair(int c) {
    return (c & ~7) + ((c & 3) << 1) + ((c >> 2) & 1);
}

__global__ __launch_bounds__(128, 4) void attention_fused_kernel(float* __restrict__ attn)
{
    __shared__ float Ks[64 * K_LD];
    __shared__ float Vs[64 * V_LD];   // pass 1: second K ping-pong buffer

    const int tid  = threadIdx.x;
    const int lane = tid & 31;
    const int warp = tid >> 5;           // 0..3
    const int g    = lane >> 2;          // 0..7
    const int t    = lane & 3;           // 0..3

    const int qt = blockIdx.x;           // 0..31
    const int h  = blockIdx.y;
    const int b  = blockIdx.z;

    const float* Qg = g_q + (size_t)b * Sc * Dc + h * HDc;
    const float* Kg = g_k + (size_t)b * Sc * Dc + h * HDc;
    const float* Vg = g_v + (size_t)b * Sc * Dc + h * HDc;

    const int qrow = qt * AT_Q + warp * 16 + g;    // this thread's first q row

    // ---- Q fragments in registers, scaled by 1/8, tf32-rounded (once) ----
    uint32_t qf[8][4];
#pragma unroll
    for (int ks = 0; ks < 8; ks++) {
        const float* q0 = Qg + (size_t)qrow * Dc + ks * 8;
        const float* q1 = Qg + (size_t)(qrow + 8) * Dc + ks * 8;
        qf[ks][0] = f2tf32(q0[t    ] * 0.125f);
        qf[ks][1] = f2tf32(q1[t    ] * 0.125f);
        qf[ks][2] = f2tf32(q0[t + 4] * 0.125f);
        qf[ks][3] = f2tf32(q1[t + 4] * 0.125f);
    }

    float m0 = -INFINITY, m1 = -INFINITY, Z0 = 0.f, Z1 = 0.f;

    // =================== PASS 1: stats only (2 k-tiles / iter) ===============
    for (int kt = 0; kt < Sc / 64; kt += 2) {
        // load tiles kt -> Ks, kt+1 -> Vs (paired-col layout, tf32)
#pragma unroll
        for (int i = 0; i < 8; i++) {
            const int f  = tid + i * 128;
            const int r  = f >> 4;
            const int c4 = (f & 15) * 4;
            const float4 k0 = *(const float4*)(Kg + (size_t)(kt * 64 + r) * Dc + c4);
            const float4 k1 = *(const float4*)(Kg + (size_t)((kt + 1) * 64 + r) * Dc + c4);
            Ks[r * K_LD + kcol_pair(c4 + 0)] = f2tf32f(k0.x);
            Ks[r * K_LD + kcol_pair(c4 + 1)] = f2tf32f(k0.y);
            Ks[r * K_LD + kcol_pair(c4 + 2)] = f2tf32f(k0.z);
            Ks[r * K_LD + kcol_pair(c4 + 3)] = f2tf32f(k0.w);
            Vs[r * V_LD + kcol_pair(c4 + 0)] = f2tf32f(k1.x);
            Vs[r * V_LD + kcol_pair(c4 + 1)] = f2tf32f(k1.y);
            Vs[r * V_LD + kcol_pair(c4 + 2)] = f2tf32f(k1.z);
            Vs[r * V_LD + kcol_pair(c4 + 3)] = f2tf32f(k1.w);
        }
        __syncthreads();

#pragma unroll
        for (int half = 0; half < 2; half++) {
            const float* Kt = half ? Vs : Ks;
            float sacc[8][4];
#pragma unroll
            for (int nt = 0; nt < 8; nt++)
#pragma unroll
                for (int i = 0; i < 4; i++) sacc[nt][i] = 0.f;

#pragma unroll
            for (int ks = 0; ks < 8; ks++) {
#pragma unroll
                for (int nt = 0; nt < 8; nt++) {
                    const float2 kp = *(const float2*)(Kt + (nt * 8 + g) * K_LD + ks * 8 + t * 2);
                    uint32_t bf[2];
                    bf[0] = __float_as_uint(kp.x);
                    bf[1] = __float_as_uint(kp.y);
                    mma_tf32(sacc[nt], qf[ks], bf);
                }
            }

            float tm0 = -INFINITY, tm1 = -INFINITY;
#pragma unroll
            for (int nt = 0; nt < 8; nt++) {
                tm0 = fmaxf(tm0, fmaxf(sacc[nt][0], sacc[nt][1]));
                tm1 = fmaxf(tm1, fmaxf(sacc[nt][2], sacc[nt][3]));
            }
            tm0 = fmaxf(tm0, __shfl_xor_sync(0xffffffff, tm0, 1));
            tm0 = fmaxf(tm0, __shfl_xor_sync(0xffffffff, tm0, 2));
            tm1 = fmaxf(tm1, __shfl_xor_sync(0xffffffff, tm1, 1));
            tm1 = fmaxf(tm1, __shfl_xor_sync(0xffffffff, tm1, 2));

            const float m0n = fmaxf(m0, tm0);
            const float m1n = fmaxf(m1, tm1);

            float s0 = 0.f, s1 = 0.f;
#pragma unroll
            for (int nt = 0; nt < 8; nt++) {
                s0 += __expf(sacc[nt][0] - m0n) + __expf(sacc[nt][1] - m0n);
                s1 += __expf(sacc[nt][2] - m1n) + __expf(sacc[nt][3] - m1n);
            }
            s0 += __shfl_xor_sync(0xffffffff, s0, 1);
            s0 += __shfl_xor_sync(0xffffffff, s0, 2);
            s1 += __shfl_xor_sync(0xffffffff, s1, 1);
            s1 += __shfl_xor_sync(0xffffffff, s1, 2);

            Z0 = Z0 * __expf(m0 - m0n) + s0;  m0 = m0n;
            Z1 = Z1 * __expf(m1 - m1n) + s1;  m1 = m1n;
        }
        __syncthreads();
    }

    const float invZ0 = 1.0f / Z0;
    const float invZ1 = 1.0f / Z1;

    // =================== PASS 2: weights (normalized) + P@V ==================
    float ctx[8][4];
#pragma unroll
    for (int nt = 0; nt < 8; nt++)
#pragma unroll
        for (int i = 0; i < 4; i++) ctx[nt][i] = 0.f;

    float* awr0 = attn + ((size_t)(b * Hc + h) * Sc + qrow) * Sc;
    float* awr1 = awr0 + (size_t)8 * Sc;

    for (int kt = 0; kt < Sc / 64; kt++) {
#pragma unroll
        for (int i = 0; i < 8; i++) {
            const int f  = tid + i * 128;
            const int r  = f >> 4;
            const int c4 = (f & 15) * 4;
            const float4 kv = *(const float4*)(Kg + (size_t)(kt * 64 + r) * Dc + c4);
            Ks[r * K_LD + kcol_pair(c4 + 0)] = f2tf32f(kv.x);
            Ks[r * K_LD + kcol_pair(c4 + 1)] = f2tf32f(kv.y);
            Ks[r * K_LD + kcol_pair(c4 + 2)] = f2tf32f(kv.z);
            Ks[r * K_LD + kcol_pair(c4 + 3)] = f2tf32f(kv.w);
            const float4 vv = *(const float4*)(Vg + (size_t)(kt * 64 + r) * Dc + c4);
            Vs[r * V_LD + c4 + 0] = f2tf32f(vv.x);
            Vs[r * V_LD + c4 + 1] = f2tf32f(vv.y);
            Vs[r * V_LD + c4 + 2] = f2tf32f(vv.z);
            Vs[r * V_LD + c4 + 3] = f2tf32f(vv.w);
        }
        __syncthreads();

        // S = Q @ K^T (bit-identical to pass 1)
        float sacc[8][4];
#pragma unroll
        for (int nt = 0; nt < 8; nt++)
#pragma unroll
            for (int i = 0; i < 4; i++) sacc[nt][i] = 0.f;

#pragma unroll
        for (int ks = 0; ks < 8; ks++) {
#pragma unroll
            for (int nt = 0; nt < 8; nt++) {
                const float2 kp = *(const float2*)(Ks + (nt * 8 + g) * K_LD + ks * 8 + t * 2);
                uint32_t bf[2];
                bf[0] = __float_as_uint(kp.x);
                bf[1] = __float_as_uint(kp.y);
                mma_tf32(sacc[nt], qf[ks], bf);
            }
        }

        // P = exp(S - m) * invZ  (final weights) and store straight from regs
#pragma unroll
        for (int nt = 0; nt < 8; nt++) {
            sacc[nt][0] = __expf(sacc[nt][0] - m0) * invZ0;
            sacc[nt][1] = __expf(sacc[nt][1] - m0) * invZ0;
            sacc[nt][2] = __expf(sacc[nt][2] - m1) * invZ1;
            sacc[nt][3] = __expf(sacc[nt][3] - m1) * invZ1;
            const int col = kt * 64 + nt * 8 + 2 * t;
            *(float2*)(awr0 + col) = make_float2(sacc[nt][0], sacc[nt][1]);
            *(float2*)(awr1 + col) = make_float2(sacc[nt][2], sacc[nt][3]);
        }

        // ctx += P @ V  (accumulator layout -> A fragment via shuffles)
        const int srcA = (lane & ~3) | (t >> 1);
        const bool odd = (t & 1);
#pragma unroll
        for (int j = 0; j < 8; j++) {
            const float e0 = __shfl_sync(0xffffffff, sacc[j][0], srcA);
            const float o0 = __shfl_sync(0xffffffff, sacc[j][1], srcA);
            const float e2 = __shfl_sync(0xffffffff, sacc[j][0], srcA + 2);
            const float o2 = __shfl_sync(0xffffffff, sacc[j][1], srcA + 2);
            const float e1 = __shfl_sync(0xffffffff, sacc[j][2], srcA);
            const float o1 = __shfl_sync(0xffffffff, sacc[j][3], srcA);
            const float e3 = __shfl_sync(0xffffffff, sacc[j][2], srcA + 2);
            const float o3 = __shfl_sync(0xffffffff, sacc[j][3], srcA + 2);
            uint32_t af[4];
            af[0] = f2tf32(odd ? o0 : e0);
            af[1] = f2tf32(odd ? o1 : e1);
            af[2] = f2tf32(odd ? o2 : e2);
            af[3] = f2tf32(odd ? o3 : e3);
#pragma unroll
            for (int nt = 0; nt < 8; nt++) {
                uint32_t bf[2];
                bf[0] = __float_as_uint(Vs[(j * 8 + t    ) * V_LD + nt * 8 + g]);
                bf[1] = __float_as_uint(Vs[(j * 8 + t + 4) * V_LD + nt * 8 + g]);
                mma_tf32(ctx[nt], af, bf);
            }
        }
        __syncthreads();
    }

    // ---- epilogue: ctx already normalized; write out ----
    float* c0 = g_ctx + (size_t)(b * Sc + qrow) * Dc + h * HDc;
    float* c1 = c0 + (size_t)8 * Dc;
#pragma unroll
    for (int nt = 0; nt < 8; nt++) {
        const int col = nt * 8 + 2 * t;
        *(float2*)(c0 + col) = make_float2(ctx[nt][0], ctx[nt][1]);
        *(float2*)(c1 + col) = make_float2(ctx[nt][2], ctx[nt][3]);
    }
}

// ---------------------------------------------------------------------------
// kernel_launch
//   d_in: x, Wq, bq, Wk, bk, Wv, bv, Wo, bo   (all fp32)
//   d_out: [ out (B*S*D) | attention_weights (B*H*S*S) ]  fp32
// ---------------------------------------------------------------------------
extern "C" void kernel_launch(void* const* d_in, const int* in_sizes, int n_in,
                              void* d_out, int out_size)
{
    (void)in_sizes; (void)n_in; (void)out_size;
    const float* x  = (const float*)d_in[0];
    const float* Wq = (const float*)d_in[1];
    const float* bq = (const float*)d_in[2];
    const float* Wk = (const float*)d_in[3];
    const float* bk = (const float*)d_in[4];
    const float* Wv = (const float*)d_in[5];
    const float* bv = (const float*)d_in[6];
    const float* Wo = (const float*)d_in[7];
    const float* bo = (const float*)d_in[8];

    float* out  = (float*)d_out;
    float* attn = out + (size_t)Bc * Sc * Dc;

    float* gq;  cudaGetSymbolAddress((void**)&gq,  g_q);
    float* gk;  cudaGetSymbolAddress((void**)&gk,  g_k);
    float* gv;  cudaGetSymbolAddress((void**)&gv,  g_v);
    float* gc;  cudaGetSymbolAddress((void**)&gc,  g_ctx);

    dim3 gemmBlock(256);

    // Q/K/V projections fused into one launch
    dim3 qkvGrid(Dc / 64, Mc / 128, 3);      // (16, 32, 3)
    gemm3_tf32_nt_bias<<<qkvGrid, gemmBlock>>>(
        x, Wq, bq, gq, Wk, bk, gk, Wv, bv, gv, Mc, Dc, Dc);

    // Fused two-pass attention: normalized weights + ctx, no extra passes
    dim3 attnGrid(Sc / AT_Q, Hc, Bc);        // (32, 16, 2)
    attention_fused_kernel<<<attnGrid, 128>>>(attn);

    // Output projection (single problem: route all three slots to it)
    dim3 oGrid(Dc / 64, Mc / 128, 1);        // (16, 32, 1)
    gemm3_tf32_nt_bias<<<oGrid, gemmBlock>>>(
        gc, Wo, bo, out, Wo, bo, out, Wo, bo, out, Mc, Dc, Dc);
}